// round 12
// baseline (speedup 1.0000x reference)
#include <cuda_runtime.h>
#include <cuda_fp16.h>
#include <cstdint>

#define EV 50000
#define EDIM 128
#define HDIM 64
#define GDIM 256
#define BSZ 512
#define SLEN 512
#define NB 4
typedef unsigned long long ull;

__device__ float g_xproj[(size_t)BSZ * SLEN * GDIM];

__device__ __forceinline__ uint32_t smem_u32(const void* p) {
    uint32_t a;
    asm("{ .reg .u64 t; cvta.to.shared.u64 t, %1; cvt.u32.u64 %0, t; }"
        : "=r"(a) : "l"(p));
    return a;
}
__device__ __forceinline__ float tanh_ap(float x) {
    float y; asm("tanh.approx.f32 %0, %1;" : "=f"(y) : "f"(x));
    return y;
}
__device__ __forceinline__ float sig_ap(float x) {
    return 0.5f * tanh_ap(0.5f * x) + 0.5f;
}
__device__ __forceinline__ void mma_f16(float* d, const uint32_t* a,
                                        const uint32_t* b) {
    asm volatile(
        "mma.sync.aligned.m16n8k16.row.col.f32.f16.f16.f32 "
        "{%0,%1,%2,%3}, {%4,%5,%6,%7}, {%8,%9}, {%0,%1,%2,%3};"
        : "+f"(d[0]), "+f"(d[1]), "+f"(d[2]), "+f"(d[3])
        : "r"(a[0]), "r"(a[1]), "r"(a[2]), "r"(a[3]), "r"(b[0]), "r"(b[1]));
}
__device__ __forceinline__ void ldsm_x4(uint32_t* r, uint32_t addr) {
    asm volatile(
        "ldmatrix.sync.aligned.m8n8.x4.shared.b16 {%0,%1,%2,%3}, [%4];"
        : "=r"(r[0]), "=r"(r[1]), "=r"(r[2]), "=r"(r[3]) : "r"(addr));
}
__device__ __forceinline__ uint32_t packh2(float lo, float hi) {
    __half2 h = __floats2half2_rn(lo, hi);
    return *(uint32_t*)&h;
}

// ============ Kernel A: embed + x@Wih0^T + bias via fp16 mma (R11 exact) =======
#define KH_PAD 136
#define KH_SMEM (64 * KH_PAD * 2 + 256 * 4)

__global__ void __launch_bounds__(256, 1)
embed_xproj_f16(const int* __restrict__ seq, const float* __restrict__ emb,
                const float* __restrict__ Wih0, const float* __restrict__ bih0,
                const float* __restrict__ bhh0) {
    extern __shared__ char smc[];
    __half* xh = (__half*)smc;
    float* bs = (float*)(smc + 64 * KH_PAD * 2);

    const int tid = threadIdx.x;
    const int lane = tid & 31, w = tid >> 5;
    const int gid = lane >> 2, tig = lane & 3;
    const int nbase = w * 32;

    if (tid < 256) bs[tid] = bih0[tid] + bhh0[tid];

    uint32_t fw[4][8][2];
#pragma unroll
    for (int nb = 0; nb < 4; nb++) {
        const float* row = Wih0 + (nbase + nb * 8 + gid) * EDIM;
#pragma unroll
        for (int kt = 0; kt < 8; kt++) {
            const int k0 = kt * 16 + 2 * tig;
            fw[nb][kt][0] = packh2(__ldg(row + k0), __ldg(row + k0 + 1));
            fw[nb][kt][1] = packh2(__ldg(row + k0 + 8), __ldg(row + k0 + 9));
        }
    }

    const int mi = lane >> 3, rr = lane & 7;
    const uint32_t aoff =
        (uint32_t)(((mi & 1) * 8 + rr) * (KH_PAD * 2) + (mi >> 1) * 16);
    const uint32_t xbase = smem_u32(xh) + aoff;

    const int mytok = tid >> 2, kq = tid & 3;
    const int ntiles = (BSZ * SLEN) / 64;
    float4 pf[8];

    auto ldx = [&](int tile) {
        int idx = __ldg(seq + tile * 64 + mytok);
        idx = idx < 0 ? 0 : (idx >= EV ? EV - 1 : idx);
        const float4* er = (const float4*)emb + (size_t)idx * 32 + kq * 8;
#pragma unroll
        for (int i = 0; i < 8; i++) pf[i] = __ldg(er + i);
    };
    auto stx = [&]() {
#pragma unroll
        for (int i = 0; i < 8; i++) {
            uint2 u;
            u.x = packh2(pf[i].x, pf[i].y);
            u.y = packh2(pf[i].z, pf[i].w);
            *(uint2*)&xh[mytok * KH_PAD + kq * 32 + i * 4] = u;
        }
    };

    int tile = blockIdx.x;
    if (tile < ntiles) ldx(tile);
    __syncthreads();
    if (tile < ntiles) stx();
    __syncthreads();

    for (; tile < ntiles; tile += gridDim.x) {
        const int nxt = tile + gridDim.x;
        if (nxt < ntiles) ldx(nxt);

        float acc[4][4][4];
#pragma unroll
        for (int mb = 0; mb < 4; mb++)
#pragma unroll
            for (int nb = 0; nb < 4; nb++)
#pragma unroll
                for (int i = 0; i < 4; i++) acc[mb][nb][i] = 0.0f;

#pragma unroll
        for (int kt = 0; kt < 8; kt++) {
            uint32_t a[4][4];
#pragma unroll
            for (int mb = 0; mb < 4; mb++)
                ldsm_x4(a[mb], xbase + mb * 16 * (KH_PAD * 2) + kt * 32);
#pragma unroll
            for (int mb = 0; mb < 4; mb++)
#pragma unroll
                for (int nb = 0; nb < 4; nb++)
                    mma_f16(acc[mb][nb], a[mb], fw[nb][kt]);
        }

#pragma unroll
        for (int mb = 0; mb < 4; mb++) {
#pragma unroll
            for (int nb = 0; nb < 4; nb++) {
                const int token = tile * 64 + mb * 16 + gid;
                const int gate = nbase + nb * 8 + 2 * tig;
                float2 bia = *(float2*)&bs[gate];
                float2 v0 = {acc[mb][nb][0] + bia.x, acc[mb][nb][1] + bia.y};
                float2 v1 = {acc[mb][nb][2] + bia.x, acc[mb][nb][3] + bia.y};
                *(float2*)&g_xproj[(size_t)token * GDIM + gate] = v0;
                *(float2*)&g_xproj[(size_t)(token + 8) * GDIM + gate] = v1;
            }
        }
        __syncthreads();
        if (nxt < ntiles) stx();
        __syncthreads();
    }
}

// ============ Kernel B: layer-specialized warps, pipelined, 1 bar/tick =========
// 512 thr: warps 0-7 = layer 0, warps 8-15 = layer 1 (lagging one step).
// Warp (group, w) owns hidden slice [8w,8w+8), n-block = gate type.
// Tick t: L0 computes h0(t) (reads h0[hp], x(t)); L1 computes h1(t-1)
// (reads h0[hp]=h0(t-1), h1[hp]=h1(t-2)); both write the hp^1 buffers; 1 bar.
#define HROWB 144
#define HBUF  (16 * HROWB)
#define KBM_SMEM (4 * HBUF + 256 * 4)

__global__ void __launch_bounds__(512, 1)
lstm_rec_mma(const float* __restrict__ Whh0, const float* __restrict__ Wih1,
             const float* __restrict__ Whh1, const float* __restrict__ bih1,
             const float* __restrict__ bhh1, const float* __restrict__ Wfc,
             const float* __restrict__ bfc, float* __restrict__ out) {
    extern __shared__ char smc[];
    float* h1f = (float*)(smc + 4 * HBUF);

    const int tid = threadIdx.x;
    const int lane = tid & 31, wid = tid >> 5;
    const bool isL1 = (wid >= 8);
    const int w = wid & 7;
    const int gid = lane >> 2, tig = lane & 3;
    const bool cellth = (gid < 4);
    const int j0 = w * 8 + 2 * tig;

    for (int i = tid; i < 2304; i += 512) ((uint32_t*)smc)[i] = 0;

    // fragments: L0 -> Whh0 (kt 0-3); L1 -> Wih1 (kt 0-3) + Whh1 (kt 4-7)
    uint32_t fw[4][8][2];
#pragma unroll
    for (int nb2 = 0; nb2 < 4; nb2++) {
        const int g = nb2 * 64 + w * 8 + gid;
        if (!isL1) {
            const float* r0 = Whh0 + g * 64;
#pragma unroll
            for (int kt = 0; kt < 4; kt++) {
                const int k0 = kt * 16 + 2 * tig;
                fw[nb2][kt][0] = packh2(__ldg(r0 + k0), __ldg(r0 + k0 + 1));
                fw[nb2][kt][1] = packh2(__ldg(r0 + k0 + 8), __ldg(r0 + k0 + 9));
            }
        } else {
            const float* rx = Wih1 + g * 64;
            const float* rh = Whh1 + g * 64;
#pragma unroll
            for (int kt = 0; kt < 4; kt++) {
                const int k0 = kt * 16 + 2 * tig;
                fw[nb2][kt][0] = packh2(__ldg(rx + k0), __ldg(rx + k0 + 1));
                fw[nb2][kt][1] = packh2(__ldg(rx + k0 + 8), __ldg(rx + k0 + 9));
                fw[nb2][kt + 4][0] = packh2(__ldg(rh + k0), __ldg(rh + k0 + 1));
                fw[nb2][kt + 4][1] = packh2(__ldg(rh + k0 + 8), __ldg(rh + k0 + 9));
            }
        }
    }
    // L1 biases
    float2 bq[4];
#pragma unroll
    for (int q = 0; q < 4; q++) {
        const int g = q * 64 + j0;
        bq[q].x = __ldg(bih1 + g) + __ldg(bhh1 + g);
        bq[q].y = __ldg(bih1 + g + 1) + __ldg(bhh1 + g + 1);
    }

    const int mi = lane >> 3, rr = lane & 7;
    const uint32_t aoff =
        (uint32_t)(((mi & 1) * 8 + rr) * HROWB + ((mi >> 1) * 8) * 2);
    const uint32_t h0base = smem_u32(smc) + aoff;
    const uint32_t h1base = smem_u32(smc) + 2 * HBUF + aoff;
    const uint32_t h0st = smem_u32(smc) + gid * HROWB + j0 * 2;
    const uint32_t h1st = smem_u32(smc) + 2 * HBUF + gid * HROWB + j0 * 2;

    const int b0i = blockIdx.x * NB;
    const float* xr = g_xproj +
        (size_t)(b0i + (cellth ? gid : 0)) * SLEN * GDIM;

    float ca = 0.f, cb = 0.f;      // cell state (c0 for L0 warps, c1 for L1)
    float hva = 0.f, hvb = 0.f;    // final h1 (L1 warps)
    float2 xq[4];
    if (!isL1 && cellth) {
#pragma unroll
        for (int q = 0; q < 4; q++) xq[q] = *(const float2*)(xr + q * 64 + j0);
    }
    uint32_t hp = 0;
    __syncthreads();

    for (int t = 0; t <= SLEN; t++) {
        if (!isL1) {
            // ---- L0: compute h0(t) ----
            if (t < SLEN) {
                float2 xn[4];
                if (cellth) {
                    const size_t toff =
                        (size_t)((t + 1 < SLEN) ? t + 1 : t) * GDIM;
#pragma unroll
                    for (int q = 0; q < 4; q++)
                        xn[q] = *(const float2*)(xr + toff + q * 64 + j0);
                }
                float acc[4][4] = {{0,0,0,0},{0,0,0,0},{0,0,0,0},{0,0,0,0}};
#pragma unroll
                for (int kt = 0; kt < 4; kt++) {
                    uint32_t a[4];
                    ldsm_x4(a, h0base + hp * HBUF + kt * 32);
#pragma unroll
                    for (int nb2 = 0; nb2 < 4; nb2++)
                        mma_f16(acc[nb2], a, fw[nb2][kt]);
                }
                if (cellth) {
                    float i0 = sig_ap(acc[0][0] + xq[0].x),
                          i1 = sig_ap(acc[0][1] + xq[0].y);
                    float f0 = sig_ap(acc[1][0] + xq[1].x),
                          f1 = sig_ap(acc[1][1] + xq[1].y);
                    float g0 = tanh_ap(acc[2][0] + xq[2].x),
                          g1 = tanh_ap(acc[2][1] + xq[2].y);
                    float o0 = sig_ap(acc[3][0] + xq[3].x),
                          o1 = sig_ap(acc[3][1] + xq[3].y);
                    ca = f0 * ca + i0 * g0;
                    cb = f1 * cb + i1 * g1;
                    uint32_t hv = packh2(o0 * tanh_ap(ca), o1 * tanh_ap(cb));
                    asm volatile("st.shared.b32 [%0], %1;"
                                 :: "r"(h0st + (hp ^ 1) * HBUF), "r"(hv)
                                 : "memory");
#pragma unroll
                    for (int q = 0; q < 4; q++) xq[q] = xn[q];
                }
            }
        } else {
            // ---- L1: compute h1(t-1) from h0(t-1)=h0[hp], h1(t-2)=h1[hp] ----
            if (t >= 1) {
                float acc[4][4] = {{0,0,0,0},{0,0,0,0},{0,0,0,0},{0,0,0,0}};
#pragma unroll
                for (int kt = 0; kt < 4; kt++) {
                    uint32_t a[4];
                    ldsm_x4(a, h0base + hp * HBUF + kt * 32);
#pragma unroll
                    for (int nb2 = 0; nb2 < 4; nb2++)
                        mma_f16(acc[nb2], a, fw[nb2][kt]);
                }
#pragma unroll
                for (int kt = 0; kt < 4; kt++) {
                    uint32_t a[4];
                    ldsm_x4(a, h1base + hp * HBUF + kt * 32);
#pragma unroll
                    for (int nb2 = 0; nb2 < 4; nb2++)
                        mma_f16(acc[nb2], a, fw[nb2][kt + 4]);
                }
                if (cellth) {
                    float i0 = sig_ap(acc[0][0] + bq[0].x),
                          i1 = sig_ap(acc[0][1] + bq[0].y);
                    float f0 = sig_ap(acc[1][0] + bq[1].x),
                          f1 = sig_ap(acc[1][1] + bq[1].y);
                    float g0 = tanh_ap(acc[2][0] + bq[2].x),
                          g1 = tanh_ap(acc[2][1] + bq[2].y);
                    float o0 = sig_ap(acc[3][0] + bq[3].x),
                          o1 = sig_ap(acc[3][1] + bq[3].y);
                    ca = f0 * ca + i0 * g0;
                    cb = f1 * cb + i1 * g1;
                    hva = o0 * tanh_ap(ca);
                    hvb = o1 * tanh_ap(cb);
                    uint32_t hv = packh2(hva, hvb);
                    asm volatile("st.shared.b32 [%0], %1;"
                                 :: "r"(h1st + (hp ^ 1) * HBUF), "r"(hv)
                                 : "memory");
                }
            }
        }
        __syncthreads();    // single barrier per tick
        hp ^= 1;
    }

    if (isL1 && cellth) {
        h1f[gid * 64 + j0] = hva;
        h1f[gid * 64 + j0 + 1] = hvb;
    }
    __syncthreads();

    if (tid < 2 * NB) {
        const int nb = tid >> 1, o = tid & 1;
        float s = bfc[o];
#pragma unroll
        for (int k = 0; k < HDIM; k++)
            s += Wfc[o * HDIM + k] * h1f[nb * HDIM + k];
        out[(b0i + nb) * 2 + o] = 1.0f / (1.0f + __expf(-s));
    }
}

// ================================ launcher =====================================
extern "C" void kernel_launch(void* const* d_in, const int* in_sizes, int n_in,
                              void* d_out, int out_size) {
    const int*   seq  = (const int*)d_in[0];
    const float* emb  = (const float*)d_in[1];
    const float* Wih0 = (const float*)d_in[2];
    const float* Whh0 = (const float*)d_in[3];
    const float* bih0 = (const float*)d_in[4];
    const float* bhh0 = (const float*)d_in[5];
    const float* Wih1 = (const float*)d_in[6];
    const float* Whh1 = (const float*)d_in[7];
    const float* bih1 = (const float*)d_in[8];
    const float* bhh1 = (const float*)d_in[9];
    const float* Wfc  = (const float*)d_in[10];
    const float* bfc  = (const float*)d_in[11];
    float* out = (float*)d_out;

    cudaFuncSetAttribute(embed_xproj_f16,
                         cudaFuncAttributeMaxDynamicSharedMemorySize, KH_SMEM);
    cudaFuncSetAttribute(lstm_rec_mma,
                         cudaFuncAttributeMaxDynamicSharedMemorySize, KBM_SMEM);

    embed_xproj_f16<<<148, 256, KH_SMEM>>>(seq, emb, Wih0, bih0, bhh0);
    lstm_rec_mma<<<BSZ / NB, 512, KBM_SMEM>>>(Whh0, Wih1, Whh1, bih1, bhh1,
                                              Wfc, bfc, out);
}

// round 13
// speedup vs baseline: 1.3542x; 1.3542x over previous
#include <cuda_runtime.h>
#include <cuda_fp16.h>
#include <cstdint>

#define EV 50000
#define EDIM 128
#define HDIM 64
#define GDIM 256
#define BSZ 512
#define SLEN 512
#define NB 4
typedef unsigned long long ull;

// xproj scratch in fp16: [token][gate], 134 MB
__device__ __half g_xproj[(size_t)BSZ * SLEN * GDIM];

__device__ __forceinline__ uint32_t smem_u32(const void* p) {
    uint32_t a;
    asm("{ .reg .u64 t; cvta.to.shared.u64 t, %1; cvt.u32.u64 %0, t; }"
        : "=r"(a) : "l"(p));
    return a;
}
__device__ __forceinline__ float tanh_ap(float x) {
    float y; asm("tanh.approx.f32 %0, %1;" : "=f"(y) : "f"(x));
    return y;
}
__device__ __forceinline__ float sig_ap(float x) {
    return 0.5f * tanh_ap(0.5f * x) + 0.5f;
}
__device__ __forceinline__ void mma_f16(float* d, const uint32_t* a,
                                        const uint32_t* b) {
    asm volatile(
        "mma.sync.aligned.m16n8k16.row.col.f32.f16.f16.f32 "
        "{%0,%1,%2,%3}, {%4,%5,%6,%7}, {%8,%9}, {%0,%1,%2,%3};"
        : "+f"(d[0]), "+f"(d[1]), "+f"(d[2]), "+f"(d[3])
        : "r"(a[0]), "r"(a[1]), "r"(a[2]), "r"(a[3]), "r"(b[0]), "r"(b[1]));
}
__device__ __forceinline__ void ldsm_x4(uint32_t* r, uint32_t addr) {
    asm volatile(
        "ldmatrix.sync.aligned.m8n8.x4.shared.b16 {%0,%1,%2,%3}, [%4];"
        : "=r"(r[0]), "=r"(r[1]), "=r"(r[2]), "=r"(r[3]) : "r"(addr));
}
__device__ __forceinline__ uint32_t packh2(float lo, float hi) {
    __half2 h = __floats2half2_rn(lo, hi);
    return *(uint32_t*)&h;
}
__device__ __forceinline__ float2 h2f2(uint32_t u) {
    return __half22float2(*(__half2*)&u);
}

// ============ Kernel A: embed + x@Wih0^T + bias, fp16 mma, fp16 output =========
#define KH_PAD 136
#define KH_SMEM (64 * KH_PAD * 2 + 256 * 4)

__global__ void __launch_bounds__(256, 1)
embed_xproj_f16(const int* __restrict__ seq, const float* __restrict__ emb,
                const float* __restrict__ Wih0, const float* __restrict__ bih0,
                const float* __restrict__ bhh0) {
    extern __shared__ char smc[];
    __half* xh = (__half*)smc;
    float* bs = (float*)(smc + 64 * KH_PAD * 2);

    const int tid = threadIdx.x;
    const int lane = tid & 31, w = tid >> 5;
    const int gid = lane >> 2, tig = lane & 3;
    const int nbase = w * 32;

    if (tid < 256) bs[tid] = bih0[tid] + bhh0[tid];

    uint32_t fw[4][8][2];
#pragma unroll
    for (int nb = 0; nb < 4; nb++) {
        const float* row = Wih0 + (nbase + nb * 8 + gid) * EDIM;
#pragma unroll
        for (int kt = 0; kt < 8; kt++) {
            const int k0 = kt * 16 + 2 * tig;
            fw[nb][kt][0] = packh2(__ldg(row + k0), __ldg(row + k0 + 1));
            fw[nb][kt][1] = packh2(__ldg(row + k0 + 8), __ldg(row + k0 + 9));
        }
    }

    const int mi = lane >> 3, rr = lane & 7;
    const uint32_t aoff =
        (uint32_t)(((mi & 1) * 8 + rr) * (KH_PAD * 2) + (mi >> 1) * 16);
    const uint32_t xbase = smem_u32(xh) + aoff;

    const int mytok = tid >> 2, kq = tid & 3;
    const int ntiles = (BSZ * SLEN) / 64;
    float4 pf[8];

    auto ldx = [&](int tile) {
        int idx = __ldg(seq + tile * 64 + mytok);
        idx = idx < 0 ? 0 : (idx >= EV ? EV - 1 : idx);
        const float4* er = (const float4*)emb + (size_t)idx * 32 + kq * 8;
#pragma unroll
        for (int i = 0; i < 8; i++) pf[i] = __ldg(er + i);
    };
    auto stx = [&]() {
#pragma unroll
        for (int i = 0; i < 8; i++) {
            uint2 u;
            u.x = packh2(pf[i].x, pf[i].y);
            u.y = packh2(pf[i].z, pf[i].w);
            *(uint2*)&xh[mytok * KH_PAD + kq * 32 + i * 4] = u;
        }
    };

    int tile = blockIdx.x;
    if (tile < ntiles) ldx(tile);
    __syncthreads();
    if (tile < ntiles) stx();
    __syncthreads();

    for (; tile < ntiles; tile += gridDim.x) {
        const int nxt = tile + gridDim.x;
        if (nxt < ntiles) ldx(nxt);

        float acc[4][4][4];
#pragma unroll
        for (int mb = 0; mb < 4; mb++)
#pragma unroll
            for (int nb = 0; nb < 4; nb++)
#pragma unroll
                for (int i = 0; i < 4; i++) acc[mb][nb][i] = 0.0f;

#pragma unroll
        for (int kt = 0; kt < 8; kt++) {
            uint32_t a[4][4];
#pragma unroll
            for (int mb = 0; mb < 4; mb++)
                ldsm_x4(a[mb], xbase + mb * 16 * (KH_PAD * 2) + kt * 32);
#pragma unroll
            for (int mb = 0; mb < 4; mb++)
#pragma unroll
                for (int nb = 0; nb < 4; nb++)
                    mma_f16(acc[mb][nb], a[mb], fw[nb][kt]);
        }

#pragma unroll
        for (int mb = 0; mb < 4; mb++) {
#pragma unroll
            for (int nb = 0; nb < 4; nb++) {
                const int token = tile * 64 + mb * 16 + gid;
                const int gate = nbase + nb * 8 + 2 * tig;
                float2 bia = *(float2*)&bs[gate];
                uint32_t v0 = packh2(acc[mb][nb][0] + bia.x,
                                     acc[mb][nb][1] + bia.y);
                uint32_t v1 = packh2(acc[mb][nb][2] + bia.x,
                                     acc[mb][nb][3] + bia.y);
                *(uint32_t*)&g_xproj[(size_t)token * GDIM + gate] = v0;
                *(uint32_t*)&g_xproj[(size_t)(token + 8) * GDIM + gate] = v1;
            }
        }
        __syncthreads();
        if (nxt < ntiles) stx();
        __syncthreads();
    }
}

// ============ Kernel B: R11 structure + split phaseB chains + fp16 x ===========
#define HROWB 144
#define HBUF  (16 * HROWB)
#define KBM_SMEM (4 * HBUF + 256 * 4)

__global__ void __launch_bounds__(256, 1)
lstm_rec_mma(const float* __restrict__ Whh0, const float* __restrict__ Wih1,
             const float* __restrict__ Whh1, const float* __restrict__ bih1,
             const float* __restrict__ bhh1, const float* __restrict__ Wfc,
             const float* __restrict__ bfc, float* __restrict__ out) {
    extern __shared__ char smc[];
    float* h1f = (float*)(smc + 4 * HBUF);

    const int tid = threadIdx.x;
    const int lane = tid & 31, w = tid >> 5;
    const int gid = lane >> 2, tig = lane & 3;
    const bool cellth = (gid < 4);
    const int j0 = w * 8 + 2 * tig;

    for (int i = tid; i < 2304; i += 256) ((uint32_t*)smc)[i] = 0;

    uint32_t fw0[4][4][2], fw1[4][8][2];
#pragma unroll
    for (int nb2 = 0; nb2 < 4; nb2++) {
        const int g = nb2 * 64 + w * 8 + gid;
        const float* r0 = Whh0 + g * 64;
        const float* rx = Wih1 + g * 64;
        const float* rh = Whh1 + g * 64;
#pragma unroll
        for (int kt = 0; kt < 4; kt++) {
            const int k0 = kt * 16 + 2 * tig;
            fw0[nb2][kt][0] = packh2(__ldg(r0 + k0), __ldg(r0 + k0 + 1));
            fw0[nb2][kt][1] = packh2(__ldg(r0 + k0 + 8), __ldg(r0 + k0 + 9));
            fw1[nb2][kt][0] = packh2(__ldg(rx + k0), __ldg(rx + k0 + 1));
            fw1[nb2][kt][1] = packh2(__ldg(rx + k0 + 8), __ldg(rx + k0 + 9));
            fw1[nb2][kt + 4][0] = packh2(__ldg(rh + k0), __ldg(rh + k0 + 1));
            fw1[nb2][kt + 4][1] = packh2(__ldg(rh + k0 + 8), __ldg(rh + k0 + 9));
        }
    }
    float2 bq[4];
#pragma unroll
    for (int q = 0; q < 4; q++) {
        const int g = q * 64 + j0;
        bq[q].x = __ldg(bih1 + g) + __ldg(bhh1 + g);
        bq[q].y = __ldg(bih1 + g + 1) + __ldg(bhh1 + g + 1);
    }

    const int mi = lane >> 3, rr = lane & 7;
    const uint32_t aoff =
        (uint32_t)(((mi & 1) * 8 + rr) * HROWB + ((mi >> 1) * 8) * 2);
    const uint32_t h0base = smem_u32(smc) + aoff;
    const uint32_t h1base = smem_u32(smc) + 2 * HBUF + aoff;
    const uint32_t h0st = smem_u32(smc) + gid * HROWB + j0 * 2;
    const uint32_t h1st = smem_u32(smc) + 2 * HBUF + gid * HROWB + j0 * 2;

    const int b0i = blockIdx.x * NB;
    const __half* xr = g_xproj +
        (size_t)(b0i + (cellth ? gid : 0)) * SLEN * GDIM;

    float c0a = 0.f, c0b = 0.f, c1a = 0.f, c1b = 0.f;
    float hva = 0.f, hvb = 0.f;
    uint32_t xq[4];                        // half2 per gate-type
    if (cellth) {
#pragma unroll
        for (int q = 0; q < 4; q++)
            xq[q] = *(const uint32_t*)(xr + q * 64 + j0);
    }
    uint32_t hp = 0;
    __syncthreads();

    for (int t = 0; t < SLEN; t++) {
        uint32_t xn[4];
        if (cellth) {
            const size_t toff = (size_t)((t + 1 < SLEN) ? t + 1 : t) * GDIM;
#pragma unroll
            for (int q = 0; q < 4; q++)
                xn[q] = *(const uint32_t*)(xr + toff + q * 64 + j0);
        }

        // ---- phaseA: preacts0 = h0[hp] @ Whh0^T ; in-register cell ----
        {
            float acc[4][4] = {{0,0,0,0},{0,0,0,0},{0,0,0,0},{0,0,0,0}};
#pragma unroll
            for (int kt = 0; kt < 4; kt++) {
                uint32_t a[4];
                ldsm_x4(a, h0base + hp * HBUF + kt * 32);
#pragma unroll
                for (int nb2 = 0; nb2 < 4; nb2++)
                    mma_f16(acc[nb2], a, fw0[nb2][kt]);
            }
            if (cellth) {
                float2 x0 = h2f2(xq[0]), x1 = h2f2(xq[1]),
                       x2 = h2f2(xq[2]), x3 = h2f2(xq[3]);
                float i0 = sig_ap(acc[0][0] + x0.x), i1 = sig_ap(acc[0][1] + x0.y);
                float f0 = sig_ap(acc[1][0] + x1.x), f1 = sig_ap(acc[1][1] + x1.y);
                float g0 = tanh_ap(acc[2][0] + x2.x), g1 = tanh_ap(acc[2][1] + x2.y);
                float o0 = sig_ap(acc[3][0] + x3.x), o1 = sig_ap(acc[3][1] + x3.y);
                c0a = f0 * c0a + i0 * g0;
                c0b = f1 * c0b + i1 * g1;
                uint32_t hv = packh2(o0 * tanh_ap(c0a), o1 * tanh_ap(c0b));
                asm volatile("st.shared.b32 [%0], %1;"
                             :: "r"(h0st + (hp ^ 1) * HBUF), "r"(hv) : "memory");
            }
        }
        __syncthreads();               // the only barrier per step

        // ---- phaseB: two independent 4-deep chains, then sum ----
        {
            float acc [4][4] = {{0,0,0,0},{0,0,0,0},{0,0,0,0},{0,0,0,0}};
            float acc2[4][4] = {{0,0,0,0},{0,0,0,0},{0,0,0,0},{0,0,0,0}};
#pragma unroll
            for (int kt = 0; kt < 4; kt++) {
                uint32_t a[4], b[4];
                ldsm_x4(a, h0base + (hp ^ 1) * HBUF + kt * 32);
                ldsm_x4(b, h1base + hp * HBUF + kt * 32);
#pragma unroll
                for (int nb2 = 0; nb2 < 4; nb2++) {
                    mma_f16(acc [nb2], a, fw1[nb2][kt]);
                    mma_f16(acc2[nb2], b, fw1[nb2][kt + 4]);
                }
            }
            if (cellth) {
                float p0a = acc[0][0] + acc2[0][0] + bq[0].x;
                float p0b = acc[0][1] + acc2[0][1] + bq[0].y;
                float p1a = acc[1][0] + acc2[1][0] + bq[1].x;
                float p1b = acc[1][1] + acc2[1][1] + bq[1].y;
                float p2a = acc[2][0] + acc2[2][0] + bq[2].x;
                float p2b = acc[2][1] + acc2[2][1] + bq[2].y;
                float p3a = acc[3][0] + acc2[3][0] + bq[3].x;
                float p3b = acc[3][1] + acc2[3][1] + bq[3].y;
                float i0 = sig_ap(p0a), i1 = sig_ap(p0b);
                float f0 = sig_ap(p1a), f1 = sig_ap(p1b);
                float g0 = tanh_ap(p2a), g1 = tanh_ap(p2b);
                float o0 = sig_ap(p3a), o1 = sig_ap(p3b);
                c1a = f0 * c1a + i0 * g0;
                c1b = f1 * c1b + i1 * g1;
                hva = o0 * tanh_ap(c1a);
                hvb = o1 * tanh_ap(c1b);
                uint32_t hv = packh2(hva, hvb);
                asm volatile("st.shared.b32 [%0], %1;"
                             :: "r"(h1st + (hp ^ 1) * HBUF), "r"(hv) : "memory");
            }
        }

        if (cellth) {
#pragma unroll
            for (int q = 0; q < 4; q++) xq[q] = xn[q];
        }
        hp ^= 1;
    }

    if (cellth) {
        h1f[gid * 64 + j0] = hva;
        h1f[gid * 64 + j0 + 1] = hvb;
    }
    __syncthreads();

    if (tid < 2 * NB) {
        const int nb = tid >> 1, o = tid & 1;
        float s = bfc[o];
#pragma unroll
        for (int k = 0; k < HDIM; k++)
            s += Wfc[o * HDIM + k] * h1f[nb * HDIM + k];
        out[(b0i + nb) * 2 + o] = 1.0f / (1.0f + __expf(-s));
    }
}

// ================================ launcher =====================================
extern "C" void kernel_launch(void* const* d_in, const int* in_sizes, int n_in,
                              void* d_out, int out_size) {
    const int*   seq  = (const int*)d_in[0];
    const float* emb  = (const float*)d_in[1];
    const float* Wih0 = (const float*)d_in[2];
    const float* Whh0 = (const float*)d_in[3];
    const float* bih0 = (const float*)d_in[4];
    const float* bhh0 = (const float*)d_in[5];
    const float* Wih1 = (const float*)d_in[6];
    const float* Whh1 = (const float*)d_in[7];
    const float* bih1 = (const float*)d_in[8];
    const float* bhh1 = (const float*)d_in[9];
    const float* Wfc  = (const float*)d_in[10];
    const float* bfc  = (const float*)d_in[11];
    float* out = (float*)d_out;

    cudaFuncSetAttribute(embed_xproj_f16,
                         cudaFuncAttributeMaxDynamicSharedMemorySize, KH_SMEM);
    cudaFuncSetAttribute(lstm_rec_mma,
                         cudaFuncAttributeMaxDynamicSharedMemorySize, KBM_SMEM);

    embed_xproj_f16<<<148, 256, KH_SMEM>>>(seq, emb, Wih0, bih0, bhh0);
    lstm_rec_mma<<<BSZ / NB, 256, KBM_SMEM>>>(Whh0, Wih1, Whh1, bih1, bhh1,
                                              Wfc, bfc, out);
}

// round 14
// speedup vs baseline: 1.4697x; 1.0853x over previous
#include <cuda_runtime.h>
#include <cuda_fp16.h>
#include <cstdint>

#define EV 50000
#define EDIM 128
#define HDIM 64
#define GDIM 256
#define BSZ 512
#define SLEN 512
#define NB 4
typedef unsigned long long ull;

// xproj scratch in fp16: [token][gate], 134 MB
__device__ __half g_xproj[(size_t)BSZ * SLEN * GDIM];

__device__ __forceinline__ uint32_t smem_u32(const void* p) {
    uint32_t a;
    asm("{ .reg .u64 t; cvta.to.shared.u64 t, %1; cvt.u32.u64 %0, t; }"
        : "=r"(a) : "l"(p));
    return a;
}
__device__ __forceinline__ float tanh_ap(float x) {
    float y; asm("tanh.approx.f32 %0, %1;" : "=f"(y) : "f"(x));
    return y;
}
__device__ __forceinline__ float sig_ap(float x) {
    return 0.5f * tanh_ap(0.5f * x) + 0.5f;
}
__device__ __forceinline__ void mma_f16(float* d, const uint32_t* a,
                                        const uint32_t* b) {
    asm volatile(
        "mma.sync.aligned.m16n8k16.row.col.f32.f16.f16.f32 "
        "{%0,%1,%2,%3}, {%4,%5,%6,%7}, {%8,%9}, {%0,%1,%2,%3};"
        : "+f"(d[0]), "+f"(d[1]), "+f"(d[2]), "+f"(d[3])
        : "r"(a[0]), "r"(a[1]), "r"(a[2]), "r"(a[3]), "r"(b[0]), "r"(b[1]));
}
__device__ __forceinline__ void ldsm_x4(uint32_t* r, uint32_t addr) {
    asm volatile(
        "ldmatrix.sync.aligned.m8n8.x4.shared.b16 {%0,%1,%2,%3}, [%4];"
        : "=r"(r[0]), "=r"(r[1]), "=r"(r[2]), "=r"(r[3]) : "r"(addr));
}
__device__ __forceinline__ uint32_t packh2(float lo, float hi) {
    __half2 h = __floats2half2_rn(lo, hi);
    return *(uint32_t*)&h;
}
__device__ __forceinline__ float2 h2f2(uint32_t u) {
    return __half22float2(*(__half2*)&u);
}

// ============ Kernel A: embed + x@Wih0^T + bias, coalesced gather/store ========
// x tile smem [64][136] halves (272B rows). out stage [64][264] halves (528B).
#define KH_PAD 136
#define KO_PAD 264
#define KH_SMEM (64 * KH_PAD * 2 + 64 * KO_PAD * 2 + 256 * 4)

__global__ void __launch_bounds__(256, 1)
embed_xproj_f16(const int* __restrict__ seq, const float* __restrict__ emb,
                const float* __restrict__ Wih0, const float* __restrict__ bih0,
                const float* __restrict__ bhh0) {
    extern __shared__ char smc[];
    __half* xh = (__half*)smc;                            // [64][136]
    __half* osg = (__half*)(smc + 64 * KH_PAD * 2);       // [64][264]
    float* bs = (float*)(smc + 64 * KH_PAD * 2 + 64 * KO_PAD * 2);

    const int tid = threadIdx.x;
    const int lane = tid & 31, w = tid >> 5;
    const int gid = lane >> 2, tig = lane & 3;
    const int nbase = w * 32;

    if (tid < 256) bs[tid] = bih0[tid] + bhh0[tid];

    // weight fragments (loaded once)
    uint32_t fw[4][8][2];
#pragma unroll
    for (int nb = 0; nb < 4; nb++) {
        const float* row = Wih0 + (nbase + nb * 8 + gid) * EDIM;
#pragma unroll
        for (int kt = 0; kt < 8; kt++) {
            const int k0 = kt * 16 + 2 * tig;
            fw[nb][kt][0] = packh2(__ldg(row + k0), __ldg(row + k0 + 1));
            fw[nb][kt][1] = packh2(__ldg(row + k0 + 8), __ldg(row + k0 + 9));
        }
    }

    const int mi = lane >> 3, rr = lane & 7;
    const uint32_t aoff =
        (uint32_t)(((mi & 1) * 8 + rr) * (KH_PAD * 2) + (mi >> 1) * 16);
    const uint32_t xbase = smem_u32(xh) + aoff;

    const int ntiles = (BSZ * SLEN) / 64;   // 4096
    float4 pf[8];

    // gather: warp w owns tokens [8w, 8w+8); one full 512B row per instruction
    auto ldx = [&](int tile) {
#pragma unroll
        for (int i = 0; i < 8; i++) {
            int idx = __ldg(seq + tile * 64 + w * 8 + i);
            idx = idx < 0 ? 0 : (idx >= EV ? EV - 1 : idx);
            pf[i] = __ldg((const float4*)emb + (size_t)idx * 32 + lane);
        }
    };
    auto stx = [&]() {
#pragma unroll
        for (int i = 0; i < 8; i++) {
            uint2 u;
            u.x = packh2(pf[i].x, pf[i].y);
            u.y = packh2(pf[i].z, pf[i].w);
            *(uint2*)&xh[(w * 8 + i) * KH_PAD + lane * 4] = u;
        }
    };

    int tile = blockIdx.x;
    if (tile < ntiles) ldx(tile);
    __syncthreads();
    if (tile < ntiles) stx();
    __syncthreads();

    for (; tile < ntiles; tile += gridDim.x) {
        const int nxt = tile + gridDim.x;
        if (nxt < ntiles) ldx(nxt);

        float acc[4][4][4];
#pragma unroll
        for (int mb = 0; mb < 4; mb++)
#pragma unroll
            for (int nb = 0; nb < 4; nb++)
#pragma unroll
                for (int i = 0; i < 4; i++) acc[mb][nb][i] = 0.0f;

#pragma unroll
        for (int kt = 0; kt < 8; kt++) {
            uint32_t a[4][4];
#pragma unroll
            for (int mb = 0; mb < 4; mb++)
                ldsm_x4(a[mb], xbase + mb * 16 * (KH_PAD * 2) + kt * 32);
#pragma unroll
            for (int mb = 0; mb < 4; mb++)
#pragma unroll
                for (int nb = 0; nb < 4; nb++)
                    mma_f16(acc[mb][nb], a[mb], fw[nb][kt]);
        }

        // stage to smem (conflict-free: 8 rows x 528B stride cover 32 banks)
#pragma unroll
        for (int mb = 0; mb < 4; mb++) {
#pragma unroll
            for (int nb = 0; nb < 4; nb++) {
                const int trow = mb * 16 + gid;
                const int gate = nbase + nb * 8 + 2 * tig;
                float2 bia = *(float2*)&bs[gate];
                *(uint32_t*)&osg[trow * KO_PAD + gate] =
                    packh2(acc[mb][nb][0] + bia.x, acc[mb][nb][1] + bia.y);
                *(uint32_t*)&osg[(trow + 8) * KO_PAD + gate] =
                    packh2(acc[mb][nb][2] + bia.x, acc[mb][nb][3] + bia.y);
            }
        }
        __syncthreads();

        // coalesced store: 32 lanes = one full 512B token row per instruction
        {
            __half* gout = g_xproj + (size_t)tile * 64 * GDIM;
#pragma unroll
            for (int i = 0; i < 8; i++) {
                const int idx = tid + i * 256;        // 0..2047
                const int token = idx >> 5, f4 = idx & 31;
                uint4 v = *(uint4*)&osg[token * KO_PAD + f4 * 8];
                *(uint4*)&gout[token * GDIM + f4 * 8] = v;
            }
        }
        if (nxt < ntiles) stx();
        __syncthreads();
    }
}

// ============ Kernel B: R11 structure (proven 372us) + fp16 x loads ============
#define HROWB 144
#define HBUF  (16 * HROWB)
#define KBM_SMEM (4 * HBUF + 256 * 4)

__global__ void __launch_bounds__(256, 1)
lstm_rec_mma(const float* __restrict__ Whh0, const float* __restrict__ Wih1,
             const float* __restrict__ Whh1, const float* __restrict__ bih1,
             const float* __restrict__ bhh1, const float* __restrict__ Wfc,
             const float* __restrict__ bfc, float* __restrict__ out) {
    extern __shared__ char smc[];
    float* h1f = (float*)(smc + 4 * HBUF);

    const int tid = threadIdx.x;
    const int lane = tid & 31, w = tid >> 5;
    const int gid = lane >> 2, tig = lane & 3;
    const bool cellth = (gid < 4);
    const int j0 = w * 8 + 2 * tig;

    for (int i = tid; i < 2304; i += 256) ((uint32_t*)smc)[i] = 0;

    uint32_t fw0[4][4][2], fw1[4][8][2];
#pragma unroll
    for (int nb2 = 0; nb2 < 4; nb2++) {
        const int g = nb2 * 64 + w * 8 + gid;
        const float* r0 = Whh0 + g * 64;
        const float* rx = Wih1 + g * 64;
        const float* rh = Whh1 + g * 64;
#pragma unroll
        for (int kt = 0; kt < 4; kt++) {
            const int k0 = kt * 16 + 2 * tig;
            fw0[nb2][kt][0] = packh2(__ldg(r0 + k0), __ldg(r0 + k0 + 1));
            fw0[nb2][kt][1] = packh2(__ldg(r0 + k0 + 8), __ldg(r0 + k0 + 9));
            fw1[nb2][kt][0] = packh2(__ldg(rx + k0), __ldg(rx + k0 + 1));
            fw1[nb2][kt][1] = packh2(__ldg(rx + k0 + 8), __ldg(rx + k0 + 9));
            fw1[nb2][kt + 4][0] = packh2(__ldg(rh + k0), __ldg(rh + k0 + 1));
            fw1[nb2][kt + 4][1] = packh2(__ldg(rh + k0 + 8), __ldg(rh + k0 + 9));
        }
    }
    float2 bq[4];
#pragma unroll
    for (int q = 0; q < 4; q++) {
        const int g = q * 64 + j0;
        bq[q].x = __ldg(bih1 + g) + __ldg(bhh1 + g);
        bq[q].y = __ldg(bih1 + g + 1) + __ldg(bhh1 + g + 1);
    }

    const int mi = lane >> 3, rr = lane & 7;
    const uint32_t aoff =
        (uint32_t)(((mi & 1) * 8 + rr) * HROWB + ((mi >> 1) * 8) * 2);
    const uint32_t h0base = smem_u32(smc) + aoff;
    const uint32_t h1base = smem_u32(smc) + 2 * HBUF + aoff;
    const uint32_t h0st = smem_u32(smc) + gid * HROWB + j0 * 2;
    const uint32_t h1st = smem_u32(smc) + 2 * HBUF + gid * HROWB + j0 * 2;

    const int b0i = blockIdx.x * NB;
    const __half* xr = g_xproj +
        (size_t)(b0i + (cellth ? gid : 0)) * SLEN * GDIM;

    float c0a = 0.f, c0b = 0.f, c1a = 0.f, c1b = 0.f;
    float hva = 0.f, hvb = 0.f;
    uint32_t xq[4];
    if (cellth) {
#pragma unroll
        for (int q = 0; q < 4; q++)
            xq[q] = *(const uint32_t*)(xr + q * 64 + j0);
    }
    uint32_t hp = 0;
    __syncthreads();

    for (int t = 0; t < SLEN; t++) {
        uint32_t xn[4];
        if (cellth) {
            const size_t toff = (size_t)((t + 1 < SLEN) ? t + 1 : t) * GDIM;
#pragma unroll
            for (int q = 0; q < 4; q++)
                xn[q] = *(const uint32_t*)(xr + toff + q * 64 + j0);
        }

        // ---- phaseA: preacts0 = h0[hp] @ Whh0^T ; in-register cell ----
        {
            float acc[4][4] = {{0,0,0,0},{0,0,0,0},{0,0,0,0},{0,0,0,0}};
#pragma unroll
            for (int kt = 0; kt < 4; kt++) {
                uint32_t a[4];
                ldsm_x4(a, h0base + hp * HBUF + kt * 32);
#pragma unroll
                for (int nb2 = 0; nb2 < 4; nb2++)
                    mma_f16(acc[nb2], a, fw0[nb2][kt]);
            }
            if (cellth) {
                float2 x0 = h2f2(xq[0]), x1 = h2f2(xq[1]),
                       x2 = h2f2(xq[2]), x3 = h2f2(xq[3]);
                float i0 = sig_ap(acc[0][0] + x0.x), i1 = sig_ap(acc[0][1] + x0.y);
                float f0 = sig_ap(acc[1][0] + x1.x), f1 = sig_ap(acc[1][1] + x1.y);
                float g0 = tanh_ap(acc[2][0] + x2.x), g1 = tanh_ap(acc[2][1] + x2.y);
                float o0 = sig_ap(acc[3][0] + x3.x), o1 = sig_ap(acc[3][1] + x3.y);
                c0a = f0 * c0a + i0 * g0;
                c0b = f1 * c0b + i1 * g1;
                uint32_t hv = packh2(o0 * tanh_ap(c0a), o1 * tanh_ap(c0b));
                asm volatile("st.shared.b32 [%0], %1;"
                             :: "r"(h0st + (hp ^ 1) * HBUF), "r"(hv) : "memory");
            }
        }
        __syncthreads();               // only barrier per step

        // ---- phaseB: preacts1 = h0[hp^1]@Wih1^T + h1[hp]@Whh1^T ; cell ----
        {
            float acc[4][4] = {{0,0,0,0},{0,0,0,0},{0,0,0,0},{0,0,0,0}};
#pragma unroll
            for (int kt = 0; kt < 4; kt++) {
                uint32_t a[4];
                ldsm_x4(a, h0base + (hp ^ 1) * HBUF + kt * 32);
#pragma unroll
                for (int nb2 = 0; nb2 < 4; nb2++)
                    mma_f16(acc[nb2], a, fw1[nb2][kt]);
            }
#pragma unroll
            for (int kt = 0; kt < 4; kt++) {
                uint32_t a[4];
                ldsm_x4(a, h1base + hp * HBUF + kt * 32);
#pragma unroll
                for (int nb2 = 0; nb2 < 4; nb2++)
                    mma_f16(acc[nb2], a, fw1[nb2][kt + 4]);
            }
            if (cellth) {
                float i0 = sig_ap(acc[0][0] + bq[0].x),
                      i1 = sig_ap(acc[0][1] + bq[0].y);
                float f0 = sig_ap(acc[1][0] + bq[1].x),
                      f1 = sig_ap(acc[1][1] + bq[1].y);
                float g0 = tanh_ap(acc[2][0] + bq[2].x),
                      g1 = tanh_ap(acc[2][1] + bq[2].y);
                float o0 = sig_ap(acc[3][0] + bq[3].x),
                      o1 = sig_ap(acc[3][1] + bq[3].y);
                c1a = f0 * c1a + i0 * g0;
                c1b = f1 * c1b + i1 * g1;
                hva = o0 * tanh_ap(c1a);
                hvb = o1 * tanh_ap(c1b);
                uint32_t hv = packh2(hva, hvb);
                asm volatile("st.shared.b32 [%0], %1;"
                             :: "r"(h1st + (hp ^ 1) * HBUF), "r"(hv) : "memory");
            }
        }

        if (cellth) {
#pragma unroll
            for (int q = 0; q < 4; q++) xq[q] = xn[q];
        }
        hp ^= 1;
    }

    if (cellth) {
        h1f[gid * 64 + j0] = hva;
        h1f[gid * 64 + j0 + 1] = hvb;
    }
    __syncthreads();

    if (tid < 2 * NB) {
        const int nb = tid >> 1, o = tid & 1;
        float s = bfc[o];
#pragma unroll
        for (int k = 0; k < HDIM; k++)
            s += Wfc[o * HDIM + k] * h1f[nb * HDIM + k];
        out[(b0i + nb) * 2 + o] = 1.0f / (1.0f + __expf(-s));
    }
}

// ================================ launcher =====================================
extern "C" void kernel_launch(void* const* d_in, const int* in_sizes, int n_in,
                              void* d_out, int out_size) {
    const int*   seq  = (const int*)d_in[0];
    const float* emb  = (const float*)d_in[1];
    const float* Wih0 = (const float*)d_in[2];
    const float* Whh0 = (const float*)d_in[3];
    const float* bih0 = (const float*)d_in[4];
    const float* bhh0 = (const float*)d_in[5];
    const float* Wih1 = (const float*)d_in[6];
    const float* Whh1 = (const float*)d_in[7];
    const float* bih1 = (const float*)d_in[8];
    const float* bhh1 = (const float*)d_in[9];
    const float* Wfc  = (const float*)d_in[10];
    const float* bfc  = (const float*)d_in[11];
    float* out = (float*)d_out;

    cudaFuncSetAttribute(embed_xproj_f16,
                         cudaFuncAttributeMaxDynamicSharedMemorySize, KH_SMEM);
    cudaFuncSetAttribute(lstm_rec_mma,
                         cudaFuncAttributeMaxDynamicSharedMemorySize, KBM_SMEM);

    embed_xproj_f16<<<148, 256, KH_SMEM>>>(seq, emb, Wih0, bih0, bhh0);
    lstm_rec_mma<<<BSZ / NB, 256, KBM_SMEM>>>(Whh0, Wih1, Whh1, bih1, bhh1,
                                              Wfc, bfc, out);
}